// round 3
// baseline (speedup 1.0000x reference)
#include <cuda_runtime.h>
#include <climits>

// Fixed problem shape: B=8, C=1, H=W=768.
#define BB    8
#define HH    768
#define WW    768
#define HWSZ  (HH * WW)          // 589824
#define NTOT  (BB * HWSZ)        // 4718592
#define N4    (NTOT / 4)         // 1179648

#define TS        32
#define TILES_X   (WW / TS)      // 24
#define TILES_Y   (HH / TS)      // 24

#define EPT   (23 * 768)         // boundary edges of one orientation per image
#define EPI   (2 * EPT)
#define NEDGE (2 * BB * EPI)     // 565248

#define LOSS_BLOCKS  2048
#define LOSS_THREADS 256

// Scratch (static __device__ arrays: allocation-free kernel_launch).
__device__ int    g_labp[NTOT];
__device__ int    g_labt[NTOT];
__device__ int    g_smin[NTOT];   // valid only at pred tile-root indices
__device__ int    g_smax[NTOT];
__device__ int    g_flag;         // zero-init at load; reset at end of k_final
__device__ double g_part[LOSS_BLOCKS];

// Exact reference arithmetic for (x + 1.0) * 0.5 without FMA contraction.
__device__ __forceinline__ float resc01(float x) {
    return __fmul_rn(__fadd_rn(x, 1.0f), 0.5f);
}

// ---------------------------------------------------------------------------
// Union-find (min-index rooting; parent <= child invariant)
// ---------------------------------------------------------------------------
__device__ __forceinline__ int uf_find(const int* L, int x) {
    int p = L[x];
    while (p != x) { x = p; p = L[x]; }
    return x;
}

__device__ __forceinline__ void uf_union(int* L, int a, int b) {
    int ra = uf_find(L, a);
    int rb = uf_find(L, b);
    while (ra != rb) {
        int hi = ra > rb ? ra : rb;
        int lo = ra > rb ? rb : ra;
        int old = atomicMin(&L[hi], lo);
        if (old == hi) break;
        ra = lo;
        rb = old;
    }
}

// Find root starting from known parent p = L[i]; compress chain (not entry i).
// Races only shorten paths toward the (stable) root -> benign.
__device__ __forceinline__ int findc_from(int* L, int p) {
    int r = p, q = L[r];
    while (q != r) { r = q; q = L[r]; }
    while (p != r) { int np = L[p]; L[p] = r; p = np; }
    return r;
}

// Shared-memory union-find.
__device__ __forceinline__ int s_find(const int* L, int x) {
    int p = L[x];
    while (p != x) { x = p; p = L[x]; }
    return x;
}

__device__ __forceinline__ void s_union(int* L, int a, int b) {
    int ra = s_find(L, a);
    int rb = s_find(L, b);
    while (ra != rb) {
        int hi = ra > rb ? ra : rb;
        int lo = ra > rb ? rb : ra;
        int old = atomicMin(&L[hi], lo);
        if (old == hi) break;
        ra = lo;
        rb = old;
    }
}

// ---------------------------------------------------------------------------
// Kernels
// ---------------------------------------------------------------------------
__global__ void k_flag(const float4* __restrict__ pred) {
    int i = blockIdx.x * blockDim.x + threadIdx.x;
    float4 v = pred[i];
    bool neg = (v.x < 0.f) | (v.y < 0.f) | (v.z < 0.f) | (v.w < 0.f);
    if (__syncthreads_or(neg) && threadIdx.x == 0) g_flag = 1;
}

// Per 32x32 tile: masks, in-tile CCL in smem, labels written as global-index
// tile roots. smin/smax initialized ONLY at pred tile-root pixels (the only
// indices that can ever be final roots).
__global__ void k_tile(const float* __restrict__ pred,
                       const float* __restrict__ target) {
    __shared__ int lp[TS * TS];
    __shared__ int lt[TS * TS];
    int lx = threadIdx.x, ly = threadIdx.y;
    int l  = ly * TS + lx;
    int gx = blockIdx.x * TS + lx;
    int gy = blockIdx.y * TS + ly;
    int b  = blockIdx.z;
    int gi = b * HWSZ + gy * WW + gx;

    bool  resc = (g_flag != 0);
    float p = pred[gi];
    float t = target[gi];
    float pp  = resc ? resc01(p) : p;
    float t01 = resc01(t);
    bool mp = pp  > 0.5f;
    bool mt = t01 > 0.5f;

    lp[l] = mp ? l : -1;
    lt[l] = mt ? l : -1;
    __syncthreads();

    if (mp) {
        if (lx > 0 && lp[l - 1]  >= 0) s_union(lp, l, l - 1);
        if (ly > 0 && lp[l - TS] >= 0) s_union(lp, l, l - TS);
    }
    if (mt) {
        if (lx > 0 && lt[l - 1]  >= 0) s_union(lt, l, l - 1);
        if (ly > 0 && lt[l - TS] >= 0) s_union(lt, l, l - TS);
    }
    __syncthreads();

    int rp = -1, rt = -1;
    if (mp) {
        int r = s_find(lp, l);
        if (r == l) { g_smin[gi] = INT_MAX; g_smax[gi] = -1; }  // root-only init
        rp = b * HWSZ + (blockIdx.y * TS + r / TS) * WW + blockIdx.x * TS + r % TS;
    }
    if (mt) {
        int r = s_find(lt, l);
        rt = b * HWSZ + (blockIdx.y * TS + r / TS) * WW + blockIdx.x * TS + r % TS;
    }
    g_labp[gi] = rp;
    g_labt[gi] = rt;
}

// Merge across tile boundaries (both masks).
__global__ void k_bmerge() {
    int tid = blockIdx.x * blockDim.x + threadIdx.x;
    if (tid >= NEDGE) return;
    int m = tid / (BB * EPI);
    int r = tid % (BB * EPI);
    int b = r / EPI;
    int e = r % EPI;
    int* L = m ? g_labt : g_labp;

    int idx, n;
    if (e < EPT) {                       // vertical boundary: (y,x)-(y,x-1)
        int bi = e / HH, y = e % HH;
        int x  = TS * (bi + 1);
        idx = b * HWSZ + y * WW + x;
        n   = idx - 1;
    } else {                             // horizontal boundary: (y,x)-(y-1,x)
        e -= EPT;
        int bi = e / WW, x = e % WW;
        int y  = TS * (bi + 1);
        idx = b * HWSZ + y * WW + x;
        n   = idx - WW;
    }
    if (L[idx] >= 0 && L[n] >= 0) uf_union(L, idx, n);
}

// Flatten pred labels to final roots (int4 in/out) + per-pred-root target
// min/max with per-thread run dedup and warp-segmented atomic aggregation.
__global__ void k_flat_agg() {
    int v = blockIdx.x * blockDim.x + threadIdx.x;   // grid covers N4 exactly
    int4 lp = ((const int4*)g_labp)[v];
    int4 lt = ((const int4*)g_labt)[v];
    int lpv[4] = {lp.x, lp.y, lp.z, lp.w};
    int ltv[4] = {lt.x, lt.y, lt.z, lt.w};
    int rp[4], rt[4];
    #pragma unroll
    for (int j = 0; j < 4; j++) {
        rp[j] = (lpv[j] >= 0) ? findc_from(g_labp, lpv[j]) : -1;
        rt[j] = (ltv[j] >= 0) ? findc_from(g_labt, ltv[j]) : -1;
    }
    ((int4*)g_labp)[v] = make_int4(rp[0], rp[1], rp[2], rp[3]);

    // Per-thread run dedup of (pred-root -> target-root min/max).
    int keys[4], mns[4], mxs[4];
    int n = 0;
    #pragma unroll
    for (int j = 0; j < 4; j++) {
        if (rp[j] >= 0 && rt[j] >= 0) {
            if (n > 0 && keys[n - 1] == rp[j]) {
                mns[n - 1] = min(mns[n - 1], rt[j]);
                mxs[n - 1] = max(mxs[n - 1], rt[j]);
            } else {
                keys[n] = rp[j]; mns[n] = rt[j]; mxs[n] = rt[j]; n++;
            }
        }
    }
    // Direct-flush all but the first run (redundant atomics are harmless).
    for (int e = 1; e < n; e++) {
        atomicMin(&g_smin[keys[e]], mns[e]);
        atomicMax(&g_smax[keys[e]], mxs[e]);
    }
    // Warp-segmented reduce of first-run entries by key; head lanes flush.
    const unsigned full = 0xffffffffu;
    int mrp = n ? keys[0] : -1;
    int mmn = n ? mns[0]  : INT_MAX;
    int mmx = n ? mxs[0]  : INT_MIN;
    #pragma unroll
    for (int off = 1; off < 32; off <<= 1) {
        int orp = __shfl_down_sync(full, mrp, off);
        int omn = __shfl_down_sync(full, mmn, off);
        int omx = __shfl_down_sync(full, mmx, off);
        if (orp == mrp) { mmn = min(mmn, omn); mmx = max(mmx, omx); }
    }
    int lane = threadIdx.x & 31;
    int prev = __shfl_up_sync(full, mrp, 1);
    if (mrp >= 0 && (lane == 0 || prev != mrp)) {
        atomicMin(&g_smin[mrp], mmn);
        atomicMax(&g_smax[mrp], mmx);
    }
}

__device__ __forceinline__ float px_loss(float p, float t, int rp, bool resc) {
    float pp  = resc ? resc01(p) : p;
    float t01 = resc01(t);
    float pl  = fabsf(pp - t01);
    float w   = 1.0f;
    // target-mask membership recomputed: rt >= 0  <=>  t01 > 0.5
    if (rp >= 0 && !(t01 > 0.5f) && g_smax[rp] > g_smin[rp]) w = 11.0f;
    return pl * w;
}

__global__ void k_loss(const float4* __restrict__ pred,
                       const float4* __restrict__ target) {
    __shared__ double sh[LOSS_THREADS];
    bool resc = (g_flag != 0);
    const int4* lp4 = (const int4*)g_labp;
    double s = 0.0;
    for (int i = blockIdx.x * blockDim.x + threadIdx.x; i < N4;
         i += gridDim.x * blockDim.x) {
        float4 p = pred[i];
        float4 t = target[i];
        int4   a = lp4[i];
        s += (double)px_loss(p.x, t.x, a.x, resc);
        s += (double)px_loss(p.y, t.y, a.y, resc);
        s += (double)px_loss(p.z, t.z, a.z, resc);
        s += (double)px_loss(p.w, t.w, a.w, resc);
    }
    sh[threadIdx.x] = s;
    __syncthreads();
    for (int off = LOSS_THREADS / 2; off > 0; off >>= 1) {
        if (threadIdx.x < off) sh[threadIdx.x] += sh[threadIdx.x + off];
        __syncthreads();
    }
    if (threadIdx.x == 0) g_part[blockIdx.x] = sh[0];
}

__global__ void k_final(float* __restrict__ out) {
    __shared__ double sh[256];
    double s = 0.0;
    for (int i = threadIdx.x; i < LOSS_BLOCKS; i += 256) s += g_part[i];
    sh[threadIdx.x] = s;
    __syncthreads();
    for (int off = 128; off > 0; off >>= 1) {
        if (threadIdx.x < off) sh[threadIdx.x] += sh[threadIdx.x + off];
        __syncthreads();
    }
    if (threadIdx.x == 0) {
        out[0] = (float)(sh[0] / (double)NTOT);
        g_flag = 0;   // reset for next replay (stream-ordered)
    }
}

// ---------------------------------------------------------------------------
extern "C" void kernel_launch(void* const* d_in, const int* in_sizes, int n_in,
                              void* d_out, int out_size) {
    const float* pred   = (const float*)d_in[0];
    const float* target = (const float*)d_in[1];
    float* out = (float*)d_out;

    k_flag<<<N4 / 256, 256>>>((const float4*)pred);
    k_tile<<<dim3(TILES_X, TILES_Y, BB), dim3(TS, TS)>>>(pred, target);
    k_bmerge<<<(NEDGE + 255) / 256, 256>>>();
    k_flat_agg<<<N4 / 256, 256>>>();
    k_loss<<<LOSS_BLOCKS, LOSS_THREADS>>>((const float4*)pred, (const float4*)target);
    k_final<<<1, 256>>>(out);
}

// round 4
// speedup vs baseline: 1.0137x; 1.0137x over previous
#include <cuda_runtime.h>
#include <climits>

// Fixed problem shape: B=8, C=1, H=W=768.
#define BB    8
#define HH    768
#define WW    768
#define HWSZ  (HH * WW)          // 589824
#define NTOT  (BB * HWSZ)        // 4718592
#define N4    (NTOT / 4)         // 1179648

#define TS        32
#define TILES_X   (WW / TS)      // 24
#define TILES_Y   (HH / TS)      // 24

#define EPT   (23 * 768)         // per-image boundary edges, one orientation
#define EPI   (2 * EPT)          // 35328 per image (both orientations)
#define NEDGE (BB * EPI)         // 282624 (each thread handles BOTH masks)

#define BG16  0xFFFFu

#define LOSS_BLOCKS  (N4 / 256)  // 4608, exact cover

// Scratch (static __device__ arrays; allocation-free kernel_launch).
__device__ unsigned g_loc[NTOT];   // packed per-pixel tile-local roots: pred | (targ<<16); BG16 = background
__device__ int      g_parp[NTOT];  // pred UF parents (valid at tile-root indices only)
__device__ int      g_part[NTOT];  // target UF parents (valid at tile-root indices only)
__device__ int2     g_mm[NTOT];    // {smin, smax} per pred root (valid at pred tile-root indices)
__device__ int      g_flag;        // rescale flag, freshly published by k_flag each run
__device__ int      g_neg, g_ctrf; // k_flag reduction state (zero-init; self-resetting)
__device__ int      g_ctr;         // k_loss last-block counter (zero-init; self-resetting)
__device__ double   g_psum[LOSS_BLOCKS];

// Exact reference arithmetic for (x + 1.0) * 0.5 without FMA contraction.
__device__ __forceinline__ float resc01(float x) {
    return __fmul_rn(__fadd_rn(x, 1.0f), 0.5f);
}

// ---------------------------------------------------------------------------
// Union-find (min-index rooting; parent <= child invariant)
// ---------------------------------------------------------------------------
__device__ __forceinline__ int uf_find(const int* L, int x) {
    int p = L[x];
    while (p != x) { x = p; p = L[x]; }
    return x;
}

// Find + full path compression (races only shorten paths -> benign).
__device__ __forceinline__ int uf_findc(int* L, int x) {
    int r = x, p = L[r];
    while (p != r) { r = p; p = L[r]; }
    while (L[x] != r) { int nx = L[x]; L[x] = r; x = nx; }
    return r;
}

__device__ __forceinline__ void uf_union(int* L, int a, int b) {
    int ra = uf_find(L, a);
    int rb = uf_find(L, b);
    while (ra != rb) {
        int hi = ra > rb ? ra : rb;
        int lo = ra > rb ? rb : ra;
        int old = atomicMin(&L[hi], lo);
        if (old == hi) break;
        ra = lo;
        rb = old;
    }
}

// Shared-memory union-find.
__device__ __forceinline__ int s_find(const int* L, int x) {
    int p = L[x];
    while (p != x) { x = p; p = L[x]; }
    return x;
}

__device__ __forceinline__ void s_union(int* L, int a, int b) {
    int ra = s_find(L, a);
    int rb = s_find(L, b);
    while (ra != rb) {
        int hi = ra > rb ? ra : rb;
        int lo = ra > rb ? rb : ra;
        int old = atomicMin(&L[hi], lo);
        if (old == hi) break;
        ra = lo;
        rb = old;
    }
}

// Reconstruct global index of a tile-local root. (ty, tx) = tile-origin coords.
__device__ __forceinline__ int rec_root(int b, int ty, int tx, unsigned loc) {
    return b * HWSZ + (ty + (int)(loc >> 5)) * WW + tx + (int)(loc & 31u);
}

// ---------------------------------------------------------------------------
// Kernels
// ---------------------------------------------------------------------------
// Publish the rescale flag fresh each run (last block pattern; state self-resets).
__global__ void k_flag(const float4* __restrict__ pred) {
    int i = blockIdx.x * blockDim.x + threadIdx.x;
    float4 v = pred[i];
    bool neg = (v.x < 0.f) | (v.y < 0.f) | (v.z < 0.f) | (v.w < 0.f);
    bool bneg = __syncthreads_or(neg);
    __shared__ bool last;
    if (threadIdx.x == 0) {
        if (bneg) atomicOr(&g_neg, 1);
        __threadfence();
        last = (atomicAdd(&g_ctrf, 1) == (int)gridDim.x - 1);
    }
    __syncthreads();
    if (last && threadIdx.x == 0) { g_flag = g_neg; g_neg = 0; g_ctrf = 0; }
}

// Per 32x32 tile: masks, in-tile CCL in smem; store packed 16-bit local roots.
// UF parents + smin/smax initialized ONLY at tile-root pixels.
__global__ void k_tile(const float* __restrict__ pred,
                       const float* __restrict__ target) {
    __shared__ int lp[TS * TS];
    __shared__ int lt[TS * TS];
    int lx = threadIdx.x, ly = threadIdx.y;
    int l  = ly * TS + lx;
    int gx = blockIdx.x * TS + lx;
    int gy = blockIdx.y * TS + ly;
    int b  = blockIdx.z;
    int gi = b * HWSZ + gy * WW + gx;

    bool  resc = (g_flag != 0);
    float p = pred[gi];
    float t = target[gi];
    float pp  = resc ? resc01(p) : p;
    float t01 = resc01(t);
    bool mp = pp  > 0.5f;
    bool mt = t01 > 0.5f;

    lp[l] = mp ? l : -1;
    lt[l] = mt ? l : -1;
    __syncthreads();

    if (mp) {
        if (lx > 0 && lp[l - 1]  >= 0) s_union(lp, l, l - 1);
        if (ly > 0 && lp[l - TS] >= 0) s_union(lp, l, l - TS);
    }
    if (mt) {
        if (lx > 0 && lt[l - 1]  >= 0) s_union(lt, l, l - 1);
        if (ly > 0 && lt[l - TS] >= 0) s_union(lt, l, l - TS);
    }
    __syncthreads();

    unsigned rp16 = BG16, rt16 = BG16;
    if (mp) {
        int r = s_find(lp, l);
        rp16 = (unsigned)r;
        if (r == l) { g_parp[gi] = gi; g_mm[gi] = make_int2(INT_MAX, -1); }
    }
    if (mt) {
        int r = s_find(lt, l);
        rt16 = (unsigned)r;
        if (r == l) g_part[gi] = gi;
    }
    g_loc[gi] = rp16 | (rt16 << 16);
}

// Merge across tile boundaries; each thread handles one edge for BOTH masks.
__global__ void k_bmerge() {
    int tid = blockIdx.x * blockDim.x + threadIdx.x;
    if (tid >= NEDGE) return;
    int b = tid / EPI;
    int e = tid % EPI;
    int y, x, ny, nx;
    if (e < EPT) {                       // vertical boundary: (y,x)-(y,x-1)
        int bi = e / HH; y = e % HH;
        x = TS * (bi + 1); ny = y; nx = x - 1;
    } else {                             // horizontal boundary: (y,x)-(y-1,x)
        e -= EPT;
        int bi = e / WW; x = e % WW;
        y = TS * (bi + 1); ny = y - 1; nx = x;
    }
    int idx = b * HWSZ + y * WW + x;
    int n   = b * HWSZ + ny * WW + nx;
    unsigned a = g_loc[idx], c = g_loc[n];
    int aty = y & ~31,  atx = x & ~31;
    int cty = ny & ~31, ctx = nx & ~31;

    if ((a & BG16) != BG16 && (c & BG16) != BG16)
        uf_union(g_parp, rec_root(b, aty, atx, a & BG16),
                          rec_root(b, cty, ctx, c & BG16));
    if ((a >> 16) != BG16 && (c >> 16) != BG16)
        uf_union(g_part, rec_root(b, aty, atx, a >> 16),
                          rec_root(b, cty, ctx, c >> 16));
}

// Aggregate per-pred-root target-root min/max over overlap pixels.
// Scalar (1 pixel/thread) for maximal memory-level parallelism; finds compress.
__global__ void k_agg() {
    int i = blockIdx.x * blockDim.x + threadIdx.x;   // exact cover of NTOT
    unsigned v = g_loc[i];
    unsigned pl = v & BG16, tl = v >> 16;
    if (pl == BG16 || tl == BG16) return;
    int b   = i / HWSZ;
    int rem = i - b * HWSZ;
    int y   = rem / WW;
    int x   = rem - y * WW;
    int ty = y & ~31, tx = x & ~31;
    int rp = uf_findc(g_parp, rec_root(b, ty, tx, pl));
    int rt = uf_findc(g_part, rec_root(b, ty, tx, tl));
    atomicMin(&g_mm[rp].x, rt);
    atomicMax(&g_mm[rp].y, rt);
}

// Weighted loss + fused final reduction (last-block pattern, fixed-order sums).
__global__ void k_loss(const float4* __restrict__ pred,
                       const float4* __restrict__ target,
                       float* __restrict__ out) {
    __shared__ double sh[256];
    bool resc = (g_flag != 0);
    int v = blockIdx.x * blockDim.x + threadIdx.x;   // exact cover of N4
    int i0  = 4 * v;
    int b   = i0 / HWSZ;
    int rem = i0 - b * HWSZ;
    int y   = rem / WW;
    int x0  = rem - y * WW;
    int ty = y & ~31, tx = x0 & ~31;   // all 4 pixels share one tile (x0 % 4 == 0)

    float4 p = pred[v];
    float4 t = target[v];
    int4   L = ((const int4*)g_loc)[v];
    float pv[4] = {p.x, p.y, p.z, p.w};
    float tv[4] = {t.x, t.y, t.z, t.w};
    unsigned lv[4] = {(unsigned)L.x, (unsigned)L.y, (unsigned)L.z, (unsigned)L.w};

    double s = 0.0;
    #pragma unroll
    for (int j = 0; j < 4; j++) {
        float pp  = resc ? resc01(pv[j]) : pv[j];
        float t01 = resc01(tv[j]);
        float pl  = fabsf(pp - t01);
        float w   = 1.0f;
        unsigned lr = lv[j] & BG16;
        if (lr != BG16 && !(t01 > 0.5f)) {          // pred fg, target bg
            int r = uf_find(g_parp, rec_root(b, ty, tx, lr));
            int2 mm = g_mm[r];
            if (mm.y > mm.x) w = 11.0f;             // merged component
        }
        s += (double)(pl * w);
    }

    sh[threadIdx.x] = s;
    __syncthreads();
    for (int off = 128; off > 0; off >>= 1) {
        if (threadIdx.x < off) sh[threadIdx.x] += sh[threadIdx.x + off];
        __syncthreads();
    }
    __shared__ bool last;
    if (threadIdx.x == 0) {
        g_psum[blockIdx.x] = sh[0];
        __threadfence();
        last = (atomicAdd(&g_ctr, 1) == (int)gridDim.x - 1);
    }
    __syncthreads();

    if (last) {
        double s2 = 0.0;
        for (int k = 0; k < LOSS_BLOCKS / 256; k++)          // fixed order
            s2 += g_psum[threadIdx.x + 256 * k];
        sh[threadIdx.x] = s2;
        __syncthreads();
        for (int off = 128; off > 0; off >>= 1) {
            if (threadIdx.x < off) sh[threadIdx.x] += sh[threadIdx.x + off];
            __syncthreads();
        }
        if (threadIdx.x == 0) {
            out[0] = (float)(sh[0] / (double)NTOT);
            g_ctr = 0;                                       // reset for next replay
        }
    }
}

// ---------------------------------------------------------------------------
extern "C" void kernel_launch(void* const* d_in, const int* in_sizes, int n_in,
                              void* d_out, int out_size) {
    const float* pred   = (const float*)d_in[0];
    const float* target = (const float*)d_in[1];
    float* out = (float*)d_out;

    k_flag<<<N4 / 256, 256>>>((const float4*)pred);
    k_tile<<<dim3(TILES_X, TILES_Y, BB), dim3(TS, TS)>>>(pred, target);
    k_bmerge<<<(NEDGE + 255) / 256, 256>>>();
    k_agg<<<NTOT / 256, 256>>>();
    k_loss<<<LOSS_BLOCKS, 256>>>((const float4*)pred, (const float4*)target, out);
}